// round 5
// baseline (speedup 1.0000x reference)
#include <cuda_runtime.h>
#include <cuda_bf16.h>
#include <cstdint>
#include <math.h>

#define B_   128
#define C_   272
#define T_   1024
#define D_   270
#define KK_  1024
#define DP   288      // padded d rows for W (3 x 96)
#define CP   320      // padded c cols for W

// Scratch (device globals; allocation-free contract). Zero-initialized.
__device__ float g_cosP[KK_ * C_];
__device__ float g_sinP[KK_ * C_];
__device__ float g_Apart[8 * D_ * C_];
__device__ __nv_bfloat16 g_Wh[DP * CP];   // softmax weights hi, [d][c], zero-padded
__device__ __nv_bfloat16 g_Wl[DP * CP];   // softmax weights lo

__device__ __forceinline__ uint32_t smem_u32(const void* p) {
    uint32_t a;
    asm("{ .reg .u64 t; cvta.to.shared.u64 t, %1; cvt.u32.u64 %0, t; }" : "=r"(a) : "l"(p));
    return a;
}

#define LDSM_X4(r, a)                                                        \
    asm volatile("ldmatrix.sync.aligned.m8n8.x4.shared.b16 {%0,%1,%2,%3}, [%4];" \
        : "=r"((r)[0]), "=r"((r)[1]), "=r"((r)[2]), "=r"((r)[3]) : "r"(a))
#define LDSM_X4_T(r, a)                                                      \
    asm volatile("ldmatrix.sync.aligned.m8n8.x4.trans.shared.b16 {%0,%1,%2,%3}, [%4];" \
        : "=r"((r)[0]), "=r"((r)[1]), "=r"((r)[2]), "=r"((r)[3]) : "r"(a))

#define MMA16816(d, a, b0v, b1v)                                             \
    asm volatile("mma.sync.aligned.m16n8k16.row.col.f32.bf16.bf16.f32 "      \
        "{%0,%1,%2,%3}, {%4,%5,%6,%7}, {%8,%9}, {%0,%1,%2,%3};"              \
        : "+f"((d)[0]), "+f"((d)[1]), "+f"((d)[2]), "+f"((d)[3])             \
        : "r"((a)[0]), "r"((a)[1]), "r"((a)[2]), "r"((a)[3]),                \
          "r"(b0v), "r"(b1v))

// ---------------------------------------------------------------------------
// Stage 1: trig table (reference-exact f32 phase, correctly-rounded cos/sin).
// ---------------------------------------------------------------------------
__global__ void trig_kernel(const float* __restrict__ loc) {
    int kl = blockIdx.x;
    int c  = threadIdx.x;
    float x = loc[2 * c];
    float y = loc[2 * c + 1];
    float kf = (float)(kl >> 5);
    float lf = (float)(kl & 31);
    float s = __fadd_rn(__fmul_rn(kf, x), __fmul_rn(lf, y));
    float p = __fmul_rn(6.28318530717958647692f, s);
    double sd, cd;
    sincos((double)p, &sd, &cd);
    g_cosP[kl * C_ + c] = (float)cd;
    g_sinP[kl * C_ + c] = (float)sd;
}

// ---------------------------------------------------------------------------
// Stage 2: A[d,c] partials (deterministic, per-kl-chunk buffers).
// ---------------------------------------------------------------------------
__global__ void a_kernel(const float* __restrict__ zre, const float* __restrict__ zim) {
    __shared__ float s_zre[16][128];
    __shared__ float s_zim[16][128];
    int d0  = blockIdx.x * 16;
    int kl0 = blockIdx.y * 128;
    int tid = threadIdx.x;

    for (int i = tid; i < 16 * 128; i += 272) {
        int dd = i >> 7, j = i & 127;
        int d = d0 + dd;
        float vr = 0.f, vi = 0.f;
        if (d < D_) {
            vr = zre[d * KK_ + kl0 + j];
            vi = zim[d * KK_ + kl0 + j];
        }
        s_zre[dd][j] = vr;
        s_zim[dd][j] = vi;
    }
    __syncthreads();

    int c = tid;
    float acc[16];
#pragma unroll
    for (int i = 0; i < 16; i++) acc[i] = 0.f;

    for (int j = 0; j < 128; j++) {
        float cv = g_cosP[(kl0 + j) * C_ + c];
        float sv = g_sinP[(kl0 + j) * C_ + c];
#pragma unroll
        for (int i = 0; i < 16; i++)
            acc[i] = fmaf(s_zre[i][j], cv, fmaf(s_zim[i][j], sv, acc[i]));
    }

#pragma unroll
    for (int i = 0; i < 16; i++) {
        int d = d0 + i;
        if (d < D_)
            g_Apart[(blockIdx.y * D_ + d) * C_ + c] = acc[i];
    }
}

// ---------------------------------------------------------------------------
// Stage 3: softmax over c per row d; emit bf16 hi/lo split weights [d][c].
// ---------------------------------------------------------------------------
__global__ void softmax_kernel() {
    int d   = blockIdx.x;
    int tid = threadIdx.x;   // 256
    __shared__ float s_red[256];

    float v0 = 0.f;
#pragma unroll
    for (int h = 0; h < 8; h++) v0 += g_Apart[(h * D_ + d) * C_ + tid];

    float v1 = __int_as_float(0xff800000);
    if (tid < C_ - 256) {
        v1 = 0.f;
#pragma unroll
        for (int h = 0; h < 8; h++) v1 += g_Apart[(h * D_ + d) * C_ + 256 + tid];
    }

    s_red[tid] = fmaxf(v0, v1);
    __syncthreads();
    for (int s = 128; s > 0; s >>= 1) {
        if (tid < s) s_red[tid] = fmaxf(s_red[tid], s_red[tid + s]);
        __syncthreads();
    }
    float mx = s_red[0];
    __syncthreads();

    float e0 = expf(v0 - mx);
    float e1 = (tid < C_ - 256) ? expf(v1 - mx) : 0.f;
    s_red[tid] = e0 + e1;
    __syncthreads();
    for (int s = 128; s > 0; s >>= 1) {
        if (tid < s) s_red[tid] += s_red[tid + s];
        __syncthreads();
    }
    float inv = 1.f / s_red[0];

    float w0 = e0 * inv;
    __nv_bfloat16 h0 = __float2bfloat16(w0);
    g_Wh[d * CP + tid] = h0;
    g_Wl[d * CP + tid] = __float2bfloat16(w0 - __bfloat162float(h0));
    if (tid < C_ - 256) {
        float w1 = e1 * inv;
        __nv_bfloat16 h1 = __float2bfloat16(w1);
        g_Wh[d * CP + 256 + tid] = h1;
        g_Wl[d * CP + 256 + tid] = __float2bfloat16(w1 - __bfloat162float(h1));
    }
}

// ---------------------------------------------------------------------------
// Stage 4: out[b,d,t] = sum_c w[d,c] * X[b,c,t] via mma.sync bf16, 3 passes.
// CTA: 96d x 256t, K chunks of 32 c (9 chunks), double-buffered smem.
// Warps 2(d) x 4(t); warp tile 48d x 64t -> 3 m-tiles x 8 n-tiles m16n8k16.
// ---------------------------------------------------------------------------
#define ASTRIDE 80
#define BSTRIDE 528
#define OFF_AH  0
#define OFF_AL  7680
#define OFF_BH  15360
#define OFF_BL  32256
#define BUFSZ   49152
#define SMEM_TOTAL (2 * BUFSZ)

__device__ __forceinline__ void bf16split2(float f0, float f1, uint32_t& hi, uint32_t& lo) {
    __nv_bfloat16 h0 = __float2bfloat16(f0);
    __nv_bfloat16 h1 = __float2bfloat16(f1);
    __nv_bfloat16 l0 = __float2bfloat16(f0 - __bfloat162float(h0));
    __nv_bfloat16 l1 = __float2bfloat16(f1 - __bfloat162float(h1));
    hi = (uint32_t)__bfloat16_as_ushort(h0) | ((uint32_t)__bfloat16_as_ushort(h1) << 16);
    lo = (uint32_t)__bfloat16_as_ushort(l0) | ((uint32_t)__bfloat16_as_ushort(l1) << 16);
}

__global__ __launch_bounds__(256, 1) void bdt_mma_kernel(const float* __restrict__ X,
                                                         float* __restrict__ out) {
    extern __shared__ __align__(16) uint8_t smem[];

    int tid  = threadIdx.x;
    int wid  = tid >> 5;
    int lane = tid & 31;
    int d0   = blockIdx.x * 96;
    int t0   = blockIdx.y * 256;
    int b    = blockIdx.z;
    int wd   = wid >> 2;       // 0..1
    int wt   = wid & 3;        // 0..3

    float acc[3][8][4];
#pragma unroll
    for (int m = 0; m < 3; m++)
#pragma unroll
        for (int n = 0; n < 8; n++)
#pragma unroll
            for (int k = 0; k < 4; k++) acc[m][n][k] = 0.f;

    uint32_t sbase = smem_u32(smem);
    uint32_t laA = (uint32_t)((lane & 15) * ASTRIDE + (lane >> 4) * 16);
    uint32_t laB = (uint32_t)((lane & 15) * BSTRIDE + (lane >> 4) * 16);

    // X prefetch mapping: thread -> (c = pc, t = pt..pt+31)
    int pc = tid >> 3;             // 0..31
    int pt = (tid & 7) * 32;       // 0..224
    const float* Xbase = X + (size_t)b * C_ * T_ + t0 + pt;

    float4 xv[8];
#pragma unroll
    for (int j = 0; j < 8; j++)
        xv[j] = *(const float4*)(Xbase + (size_t)pc * T_ + j * 4);

    for (int ch = 0; ch < 9; ch++) {
        int c0 = ch * 32;
        int nc = (ch == 8) ? 16 : 32;
        uint32_t bufo = (uint32_t)(ch & 1) * BUFSZ;
        uint8_t* buf = smem + bufo;

        // ---- stage B: X chunk -> bf16 hi/lo [c][t] ----
        if (pc < nc) {
            uint32_t off = (uint32_t)(pc * BSTRIDE + pt * 2);
#pragma unroll
            for (int j = 0; j < 4; j++) {
                uint32_t h0, h1, l0, l1;
                bf16split2(xv[2 * j].x, xv[2 * j].y, h0, l0);
                bf16split2(xv[2 * j].z, xv[2 * j].w, h1, l1);
                uint32_t h2, h3, l2, l3;
                bf16split2(xv[2 * j + 1].x, xv[2 * j + 1].y, h2, l2);
                bf16split2(xv[2 * j + 1].z, xv[2 * j + 1].w, h3, l3);
                *(uint4*)(buf + OFF_BH + off + j * 16) = make_uint4(h0, h1, h2, h3);
                *(uint4*)(buf + OFF_BL + off + j * 16) = make_uint4(l0, l1, l2, l3);
            }
        }
        // ---- stage A: W chunk (L2-hot) ----
        for (int i = tid; i < 96 * 4; i += 256) {
            int row = i >> 2, seg = i & 3;
            if (seg * 8 < nc) {
                int src = (d0 + row) * CP + c0 + seg * 8;
                uint4 vh = *(const uint4*)&g_Wh[src];
                uint4 vl = *(const uint4*)&g_Wl[src];
                uint32_t off = (uint32_t)(row * ASTRIDE + seg * 16);
                *(uint4*)(buf + OFF_AH + off) = vh;
                *(uint4*)(buf + OFF_AL + off) = vl;
            }
        }
        __syncthreads();

        // ---- prefetch next chunk (overlaps MMA below) ----
        if (ch < 8) {
            int ncn = (ch == 7) ? 16 : 32;
            if (pc < ncn) {
#pragma unroll
                for (int j = 0; j < 8; j++)
                    xv[j] = *(const float4*)(Xbase + (size_t)((ch + 1) * 32 + pc) * T_ + j * 4);
            }
        }

        // ---- mma ----
        uint32_t Ah = sbase + bufo + OFF_AH + (uint32_t)(wd * 48 * ASTRIDE) + laA;
        uint32_t Al = sbase + bufo + OFF_AL + (uint32_t)(wd * 48 * ASTRIDE) + laA;
        uint32_t Bh = sbase + bufo + OFF_BH + (uint32_t)(wt * 128) + laB;
        uint32_t Bl = sbase + bufo + OFF_BL + (uint32_t)(wt * 128) + laB;

        int nks = nc >> 4;
        for (int ks = 0; ks < nks; ks++) {
            uint32_t ao = (uint32_t)(ks * 32);
            uint32_t bo = (uint32_t)(ks * 16 * BSTRIDE);

            uint32_t ah[3][4], al[3][4];
#pragma unroll
            for (int mt = 0; mt < 3; mt++) {
                LDSM_X4(ah[mt], Ah + (uint32_t)(mt * 16 * ASTRIDE) + ao);
                LDSM_X4(al[mt], Al + (uint32_t)(mt * 16 * ASTRIDE) + ao);
            }
#pragma unroll
            for (int ntg = 0; ntg < 2; ntg++) {
                uint32_t bh[8], bl[8];
                LDSM_X4_T(bh,     Bh + bo + (uint32_t)(ntg * 64));
                LDSM_X4_T(bh + 4, Bh + bo + (uint32_t)(ntg * 64) + 32);
                LDSM_X4_T(bl,     Bl + bo + (uint32_t)(ntg * 64));
                LDSM_X4_T(bl + 4, Bl + bo + (uint32_t)(ntg * 64) + 32);
#pragma unroll
                for (int mt = 0; mt < 3; mt++) {
#pragma unroll
                    for (int q = 0; q < 4; q++) {
                        int nt = ntg * 4 + q;
                        MMA16816(acc[mt][nt], ah[mt], bh[2 * q], bh[2 * q + 1]);
                        MMA16816(acc[mt][nt], ah[mt], bl[2 * q], bl[2 * q + 1]);
                        MMA16816(acc[mt][nt], al[mt], bh[2 * q], bh[2 * q + 1]);
                    }
                }
            }
        }
    }

    // ---- epilogue: fragment rows = d, cols = t ----
#pragma unroll
    for (int mt = 0; mt < 3; mt++) {
        int dr = d0 + wd * 48 + mt * 16 + (lane >> 2);
#pragma unroll
        for (int nt = 0; nt < 8; nt++) {
            int tt = t0 + wt * 64 + nt * 8 + (lane & 3) * 2;
            if (dr < D_)
                *(float2*)(out + ((size_t)b * D_ + dr) * T_ + tt) =
                    make_float2(acc[mt][nt][0], acc[mt][nt][1]);
            if (dr + 8 < D_)
                *(float2*)(out + ((size_t)b * D_ + dr + 8) * T_ + tt) =
                    make_float2(acc[mt][nt][2], acc[mt][nt][3]);
        }
    }
}

// ---------------------------------------------------------------------------
extern "C" void kernel_launch(void* const* d_in, const int* in_sizes, int n_in,
                              void* d_out, int out_size) {
    const float* X   = (const float*)d_in[0];
    const float* loc = (const float*)d_in[1];
    const float* zre = (const float*)d_in[2];
    const float* zim = (const float*)d_in[3];
    float* out = (float*)d_out;

    cudaFuncSetAttribute(bdt_mma_kernel, cudaFuncAttributeMaxDynamicSharedMemorySize, SMEM_TOTAL);

    trig_kernel<<<KK_, C_>>>(loc);
    a_kernel<<<dim3(17, 8), 272>>>(zre, zim);
    softmax_kernel<<<D_, 256>>>();
    bdt_mma_kernel<<<dim3(3, 4, B_), 256, SMEM_TOTAL>>>(X, out);
}

// round 7
// speedup vs baseline: 1.3575x; 1.3575x over previous
#include <cuda_runtime.h>
#include <cuda_bf16.h>
#include <cstdint>
#include <math.h>

#define B_   128
#define C_   272
#define T_   1024
#define D_   270
#define KK_  1024
#define DP   288      // padded d rows for W (3 x 96)
#define CP   320      // padded c cols for W

// Scratch (device globals; allocation-free contract). Zero-initialized.
__device__ float g_cosP[KK_ * C_];
__device__ float g_sinP[KK_ * C_];
__device__ float g_Apart[8 * D_ * C_];
__device__ __nv_bfloat16 g_Wh[DP * CP];   // softmax weights hi, [d][c], zero-padded
__device__ __nv_bfloat16 g_Wl[DP * CP];   // softmax weights lo

__device__ __forceinline__ uint32_t smem_u32(const void* p) {
    uint32_t a;
    asm("{ .reg .u64 t; cvta.to.shared.u64 t, %1; cvt.u32.u64 %0, t; }" : "=r"(a) : "l"(p));
    return a;
}

#define LDSM_X4(r, a)                                                        \
    asm volatile("ldmatrix.sync.aligned.m8n8.x4.shared.b16 {%0,%1,%2,%3}, [%4];" \
        : "=r"((r)[0]), "=r"((r)[1]), "=r"((r)[2]), "=r"((r)[3]) : "r"(a))
#define LDSM_X4_T(r, a)                                                      \
    asm volatile("ldmatrix.sync.aligned.m8n8.x4.trans.shared.b16 {%0,%1,%2,%3}, [%4];" \
        : "=r"((r)[0]), "=r"((r)[1]), "=r"((r)[2]), "=r"((r)[3]) : "r"(a))

#define MMA16816(d, a, b0v, b1v)                                             \
    asm volatile("mma.sync.aligned.m16n8k16.row.col.f32.bf16.bf16.f32 "      \
        "{%0,%1,%2,%3}, {%4,%5,%6,%7}, {%8,%9}, {%0,%1,%2,%3};"              \
        : "+f"((d)[0]), "+f"((d)[1]), "+f"((d)[2]), "+f"((d)[3])             \
        : "r"((a)[0]), "r"((a)[1]), "r"((a)[2]), "r"((a)[3]),                \
          "r"(b0v), "r"(b1v))

// ---------------------------------------------------------------------------
// Stage 1: trig table (reference-exact f32 phase, correctly-rounded cos/sin).
// ---------------------------------------------------------------------------
__global__ void trig_kernel(const float* __restrict__ loc) {
    int kl = blockIdx.x;
    int c  = threadIdx.x;
    float x = loc[2 * c];
    float y = loc[2 * c + 1];
    float kf = (float)(kl >> 5);
    float lf = (float)(kl & 31);
    float s = __fadd_rn(__fmul_rn(kf, x), __fmul_rn(lf, y));
    float p = __fmul_rn(6.28318530717958647692f, s);
    double sd, cd;
    sincos((double)p, &sd, &cd);
    g_cosP[kl * C_ + c] = (float)cd;
    g_sinP[kl * C_ + c] = (float)sd;
}

// ---------------------------------------------------------------------------
// Stage 2: A[d,c] partials (deterministic, per-kl-chunk buffers).
// ---------------------------------------------------------------------------
__global__ void a_kernel(const float* __restrict__ zre, const float* __restrict__ zim) {
    __shared__ float s_zre[16][128];
    __shared__ float s_zim[16][128];
    int d0  = blockIdx.x * 16;
    int kl0 = blockIdx.y * 128;
    int tid = threadIdx.x;

    for (int i = tid; i < 16 * 128; i += 272) {
        int dd = i >> 7, j = i & 127;
        int d = d0 + dd;
        float vr = 0.f, vi = 0.f;
        if (d < D_) {
            vr = zre[d * KK_ + kl0 + j];
            vi = zim[d * KK_ + kl0 + j];
        }
        s_zre[dd][j] = vr;
        s_zim[dd][j] = vi;
    }
    __syncthreads();

    int c = tid;
    float acc[16];
#pragma unroll
    for (int i = 0; i < 16; i++) acc[i] = 0.f;

    for (int j = 0; j < 128; j++) {
        float cv = g_cosP[(kl0 + j) * C_ + c];
        float sv = g_sinP[(kl0 + j) * C_ + c];
#pragma unroll
        for (int i = 0; i < 16; i++)
            acc[i] = fmaf(s_zre[i][j], cv, fmaf(s_zim[i][j], sv, acc[i]));
    }

#pragma unroll
    for (int i = 0; i < 16; i++) {
        int d = d0 + i;
        if (d < D_)
            g_Apart[(blockIdx.y * D_ + d) * C_ + c] = acc[i];
    }
}

// ---------------------------------------------------------------------------
// Stage 3: softmax over c per row d; emit bf16 hi/lo split weights [d][c].
// ---------------------------------------------------------------------------
__global__ void softmax_kernel() {
    int d   = blockIdx.x;
    int tid = threadIdx.x;   // 256
    __shared__ float s_red[256];

    float v0 = 0.f;
#pragma unroll
    for (int h = 0; h < 8; h++) v0 += g_Apart[(h * D_ + d) * C_ + tid];

    float v1 = __int_as_float(0xff800000);
    if (tid < C_ - 256) {
        v1 = 0.f;
#pragma unroll
        for (int h = 0; h < 8; h++) v1 += g_Apart[(h * D_ + d) * C_ + 256 + tid];
    }

    s_red[tid] = fmaxf(v0, v1);
    __syncthreads();
    for (int s = 128; s > 0; s >>= 1) {
        if (tid < s) s_red[tid] = fmaxf(s_red[tid], s_red[tid + s]);
        __syncthreads();
    }
    float mx = s_red[0];
    __syncthreads();

    float e0 = expf(v0 - mx);
    float e1 = (tid < C_ - 256) ? expf(v1 - mx) : 0.f;
    s_red[tid] = e0 + e1;
    __syncthreads();
    for (int s = 128; s > 0; s >>= 1) {
        if (tid < s) s_red[tid] += s_red[tid + s];
        __syncthreads();
    }
    float inv = 1.f / s_red[0];

    float w0 = e0 * inv;
    __nv_bfloat16 h0 = __float2bfloat16(w0);
    g_Wh[d * CP + tid] = h0;
    g_Wl[d * CP + tid] = __float2bfloat16(w0 - __bfloat162float(h0));
    if (tid < C_ - 256) {
        float w1 = e1 * inv;
        __nv_bfloat16 h1 = __float2bfloat16(w1);
        g_Wh[d * CP + 256 + tid] = h1;
        g_Wl[d * CP + 256 + tid] = __float2bfloat16(w1 - __bfloat162float(h1));
    }
}

// ---------------------------------------------------------------------------
// Stage 4: out[b,d,t] = sum_c w[d,c] * X[b,c,t] via mma.sync bf16, 3 passes.
// CTA: 96d x 128t, K chunks of 32 c (9 chunks), DOUBLE-BUFFERED smem,
// one __syncthreads per chunk. Warps 2(d) x 4(t), warp tile 48d x 32t.
// ---------------------------------------------------------------------------
#define ASTRIDE 80
#define BSTRIDE 272
#define OFF_AH  0
#define OFF_AL  7680
#define OFF_BH  15360
#define OFF_BL  24064
#define BUFSZ   32768
#define SMEM_TOTAL (2 * BUFSZ)

__device__ __forceinline__ void bf16split2(float f0, float f1, uint32_t& hi, uint32_t& lo) {
    __nv_bfloat16 h0 = __float2bfloat16(f0);
    __nv_bfloat16 h1 = __float2bfloat16(f1);
    __nv_bfloat16 l0 = __float2bfloat16(f0 - __bfloat162float(h0));
    __nv_bfloat16 l1 = __float2bfloat16(f1 - __bfloat162float(h1));
    hi = (uint32_t)__bfloat16_as_ushort(h0) | ((uint32_t)__bfloat16_as_ushort(h1) << 16);
    lo = (uint32_t)__bfloat16_as_ushort(l0) | ((uint32_t)__bfloat16_as_ushort(l1) << 16);
}

__global__ __launch_bounds__(256, 2) void bdt_mma_kernel(const float* __restrict__ X,
                                                         float* __restrict__ out) {
    extern __shared__ __align__(16) uint8_t smem[];

    int tid  = threadIdx.x;
    int wid  = tid >> 5;
    int lane = tid & 31;
    int d0   = blockIdx.x * 96;
    int t0   = blockIdx.y * 128;
    int b    = blockIdx.z;
    int wd   = wid >> 2;       // 0..1
    int wt   = wid & 3;        // 0..3

    float acc[3][4][4];
#pragma unroll
    for (int m = 0; m < 3; m++)
#pragma unroll
        for (int n = 0; n < 4; n++)
#pragma unroll
            for (int k = 0; k < 4; k++) acc[m][n][k] = 0.f;

    uint32_t sbase = smem_u32(smem);
    uint32_t laA = (uint32_t)((lane & 15) * ASTRIDE + (lane >> 4) * 16);
    uint32_t laB = (uint32_t)((lane & 15) * BSTRIDE + (lane >> 4) * 16);

    // X staging mapping: thread -> (c = pc, t = pt..pt+15)
    int pc = tid >> 3;             // 0..31
    int pt = (tid & 7) * 16;       // 0..112
    const float* Xbase = X + (size_t)b * C_ * T_ + t0 + pt;

    float4 xv[4];

    // ---------- helpers as lambdas ----------
    auto stsX = [&](uint8_t* buf) {
        uint32_t hi[4], lo[4];
#pragma unroll
        for (int j = 0; j < 2; j++) {
            bf16split2(xv[2 * j].x, xv[2 * j].y, hi[2 * j], lo[2 * j]);
            bf16split2(xv[2 * j].z, xv[2 * j].w, hi[2 * j + 1], lo[2 * j + 1]);
        }
        uint32_t hi2[4], lo2[4];
#pragma unroll
        for (int j = 0; j < 2; j++) {
            bf16split2(xv[2 * j + 1].x, xv[2 * j + 1].y, hi2[2 * j], lo2[2 * j]);
            bf16split2(xv[2 * j + 1].z, xv[2 * j + 1].w, hi2[2 * j + 1], lo2[2 * j + 1]);
        }
        uint32_t off = (uint32_t)(pc * BSTRIDE + pt * 2);
        *(uint4*)(buf + OFF_BH + off)      = make_uint4(hi[0], hi[1], hi2[0], hi2[1]);
        *(uint4*)(buf + OFF_BH + off + 16) = make_uint4(hi[2], hi[3], hi2[2], hi2[3]);
        *(uint4*)(buf + OFF_BL + off)      = make_uint4(lo[0], lo[1], lo2[0], lo2[1]);
        *(uint4*)(buf + OFF_BL + off + 16) = make_uint4(lo[2], lo[3], lo2[2], lo2[3]);
    };
    auto stageW = [&](uint8_t* buf, int c0n, int ncn) {
#pragma unroll
        for (int k = 0; k < 3; k++) {
            int i = tid + k * 256;          // 0..767
            int half = (i >= 384);
            int j = half ? i - 384 : i;     // 0..383
            int row = j >> 2, seg = j & 3;
            if (seg * 8 < ncn) {
                int src = (d0 + row) * CP + c0n + seg * 8;
                uint4 v = half ? *(const uint4*)&g_Wl[src] : *(const uint4*)&g_Wh[src];
                *(uint4*)(buf + (half ? OFF_AL : OFF_AH) + (uint32_t)(row * ASTRIDE + seg * 16)) = v;
            }
        }
    };

    // ---------- prologue: stage chunk 0, prefetch chunk 1 ----------
#pragma unroll
    for (int j = 0; j < 4; j++)
        xv[j] = *(const float4*)(Xbase + (size_t)pc * T_ + j * 4);
    stsX(smem);
    stageW(smem, 0, 32);
#pragma unroll
    for (int j = 0; j < 4; j++)
        xv[j] = *(const float4*)(Xbase + (size_t)(32 + pc) * T_ + j * 4);
    __syncthreads();

    // ---------- main loop: one sync per chunk ----------
    for (int ch = 0; ch < 9; ch++) {
        int cur = ch & 1;
        uint32_t bufo = (uint32_t)cur * BUFSZ;
        int nc = (ch == 8) ? 16 : 32;

        // stage chunk ch+1 into the other buffer (overlaps MMA of chunk ch)
        if (ch < 8) {
            int ncn = (ch == 7) ? 16 : 32;
            uint8_t* nbuf = smem + (uint32_t)(cur ^ 1) * BUFSZ;
            if (pc < ncn) stsX(nbuf);
            stageW(nbuf, (ch + 1) * 32, ncn);
            if (ch < 7) {
                int nc2 = (ch == 6) ? 16 : 32;
                if (pc < nc2) {
#pragma unroll
                    for (int j = 0; j < 4; j++)
                        xv[j] = *(const float4*)(Xbase + (size_t)((ch + 2) * 32 + pc) * T_ + j * 4);
                }
            }
        }

        // ---- mma on buf[cur] ----
        uint32_t Ah = sbase + bufo + OFF_AH + (uint32_t)(wd * 48 * ASTRIDE) + laA;
        uint32_t Al = sbase + bufo + OFF_AL + (uint32_t)(wd * 48 * ASTRIDE) + laA;
        uint32_t Bh = sbase + bufo + OFF_BH + (uint32_t)(wt * 64) + laB;
        uint32_t Bl = sbase + bufo + OFF_BL + (uint32_t)(wt * 64) + laB;

        int nks = nc >> 4;
        for (int ks = 0; ks < nks; ks++) {
            uint32_t ao = (uint32_t)(ks * 32);
            uint32_t bo = (uint32_t)(ks * 16 * BSTRIDE);

            uint32_t ah[3][4], al[3][4];
#pragma unroll
            for (int mt = 0; mt < 3; mt++) {
                LDSM_X4(ah[mt], Ah + (uint32_t)(mt * 16 * ASTRIDE) + ao);
                LDSM_X4(al[mt], Al + (uint32_t)(mt * 16 * ASTRIDE) + ao);
            }
            uint32_t bh[8], bl[8];
            LDSM_X4_T(bh,     Bh + bo);
            LDSM_X4_T(bh + 4, Bh + bo + 32);
            LDSM_X4_T(bl,     Bl + bo);
            LDSM_X4_T(bl + 4, Bl + bo + 32);

#pragma unroll
            for (int mt = 0; mt < 3; mt++) {
#pragma unroll
                for (int nt = 0; nt < 4; nt++) {
                    MMA16816(acc[mt][nt], ah[mt], bh[2 * nt], bh[2 * nt + 1]);
                    MMA16816(acc[mt][nt], ah[mt], bl[2 * nt], bl[2 * nt + 1]);
                    MMA16816(acc[mt][nt], al[mt], bh[2 * nt], bh[2 * nt + 1]);
                }
            }
        }
        __syncthreads();
    }

    // ---- epilogue: fragment rows = d, cols = t ----
#pragma unroll
    for (int mt = 0; mt < 3; mt++) {
        int dr = d0 + wd * 48 + mt * 16 + (lane >> 2);
#pragma unroll
        for (int nt = 0; nt < 4; nt++) {
            int tt = t0 + wt * 32 + nt * 8 + (lane & 3) * 2;
            if (dr < D_)
                *(float2*)(out + ((size_t)b * D_ + dr) * T_ + tt) =
                    make_float2(acc[mt][nt][0], acc[mt][nt][1]);
            if (dr + 8 < D_)
                *(float2*)(out + ((size_t)b * D_ + dr + 8) * T_ + tt) =
                    make_float2(acc[mt][nt][2], acc[mt][nt][3]);
        }
    }
}

// ---------------------------------------------------------------------------
extern "C" void kernel_launch(void* const* d_in, const int* in_sizes, int n_in,
                              void* d_out, int out_size) {
    const float* X   = (const float*)d_in[0];
    const float* loc = (const float*)d_in[1];
    const float* zre = (const float*)d_in[2];
    const float* zim = (const float*)d_in[3];
    float* out = (float*)d_out;

    cudaFuncSetAttribute(bdt_mma_kernel, cudaFuncAttributeMaxDynamicSharedMemorySize, SMEM_TOTAL);

    trig_kernel<<<KK_, C_>>>(loc);
    a_kernel<<<dim3(17, 8), 272>>>(zre, zim);
    softmax_kernel<<<D_, 256>>>();
    bdt_mma_kernel<<<dim3(3, 8, B_), 256, SMEM_TOTAL>>>(X, out);
}

// round 8
// speedup vs baseline: 1.5849x; 1.1675x over previous
#include <cuda_runtime.h>
#include <cuda_bf16.h>
#include <cuda_fp16.h>
#include <cstdint>
#include <math.h>

#define B_   128
#define C_   272
#define T_   1024
#define D_   270
#define KK_  1024
#define DP   288      // padded d rows for W (3 x 96)
#define CP   320      // padded c cols for W

// Scratch (device globals; allocation-free contract). Zero-initialized.
__device__ float g_cosP[KK_ * C_];
__device__ float g_sinP[KK_ * C_];
__device__ float g_Apart[8 * D_ * C_];
__device__ __half g_Wh[DP * CP];   // softmax weights hi (fp16), [d][c], zero-padded
__device__ __half g_Wl[DP * CP];   // softmax weights lo (fp16)

__device__ __forceinline__ uint32_t smem_u32(const void* p) {
    uint32_t a;
    asm("{ .reg .u64 t; cvta.to.shared.u64 t, %1; cvt.u32.u64 %0, t; }" : "=r"(a) : "l"(p));
    return a;
}

#define LDSM_X4(r, a)                                                        \
    asm volatile("ldmatrix.sync.aligned.m8n8.x4.shared.b16 {%0,%1,%2,%3}, [%4];" \
        : "=r"((r)[0]), "=r"((r)[1]), "=r"((r)[2]), "=r"((r)[3]) : "r"(a))
#define LDSM_X4_T(r, a)                                                      \
    asm volatile("ldmatrix.sync.aligned.m8n8.x4.trans.shared.b16 {%0,%1,%2,%3}, [%4];" \
        : "=r"((r)[0]), "=r"((r)[1]), "=r"((r)[2]), "=r"((r)[3]) : "r"(a))

#define MMA16816F(d, a, b0v, b1v)                                            \
    asm volatile("mma.sync.aligned.m16n8k16.row.col.f32.f16.f16.f32 "        \
        "{%0,%1,%2,%3}, {%4,%5,%6,%7}, {%8,%9}, {%0,%1,%2,%3};"              \
        : "+f"((d)[0]), "+f"((d)[1]), "+f"((d)[2]), "+f"((d)[3])             \
        : "r"((a)[0]), "r"((a)[1]), "r"((a)[2]), "r"((a)[3]),                \
          "r"(b0v), "r"(b1v))

// ---------------------------------------------------------------------------
// Stage 1: trig table (reference-exact f32 phase, correctly-rounded cos/sin).
// ---------------------------------------------------------------------------
__global__ void trig_kernel(const float* __restrict__ loc) {
    int kl = blockIdx.x;
    int c  = threadIdx.x;
    float x = loc[2 * c];
    float y = loc[2 * c + 1];
    float kf = (float)(kl >> 5);
    float lf = (float)(kl & 31);
    float s = __fadd_rn(__fmul_rn(kf, x), __fmul_rn(lf, y));
    float p = __fmul_rn(6.28318530717958647692f, s);
    double sd, cd;
    sincos((double)p, &sd, &cd);
    g_cosP[kl * C_ + c] = (float)cd;
    g_sinP[kl * C_ + c] = (float)sd;
}

// ---------------------------------------------------------------------------
// Stage 2: A[d,c] partials (deterministic, per-kl-chunk buffers).
// ---------------------------------------------------------------------------
__global__ void a_kernel(const float* __restrict__ zre, const float* __restrict__ zim) {
    __shared__ float s_zre[16][128];
    __shared__ float s_zim[16][128];
    int d0  = blockIdx.x * 16;
    int kl0 = blockIdx.y * 128;
    int tid = threadIdx.x;

    for (int i = tid; i < 16 * 128; i += 272) {
        int dd = i >> 7, j = i & 127;
        int d = d0 + dd;
        float vr = 0.f, vi = 0.f;
        if (d < D_) {
            vr = zre[d * KK_ + kl0 + j];
            vi = zim[d * KK_ + kl0 + j];
        }
        s_zre[dd][j] = vr;
        s_zim[dd][j] = vi;
    }
    __syncthreads();

    int c = tid;
    float acc[16];
#pragma unroll
    for (int i = 0; i < 16; i++) acc[i] = 0.f;

    for (int j = 0; j < 128; j++) {
        float cv = g_cosP[(kl0 + j) * C_ + c];
        float sv = g_sinP[(kl0 + j) * C_ + c];
#pragma unroll
        for (int i = 0; i < 16; i++)
            acc[i] = fmaf(s_zre[i][j], cv, fmaf(s_zim[i][j], sv, acc[i]));
    }

#pragma unroll
    for (int i = 0; i < 16; i++) {
        int d = d0 + i;
        if (d < D_)
            g_Apart[(blockIdx.y * D_ + d) * C_ + c] = acc[i];
    }
}

// ---------------------------------------------------------------------------
// Stage 3: softmax over c per row d; emit fp16 hi/lo split weights [d][c].
// ---------------------------------------------------------------------------
__global__ void softmax_kernel() {
    int d   = blockIdx.x;
    int tid = threadIdx.x;   // 256
    __shared__ float s_red[256];

    float v0 = 0.f;
#pragma unroll
    for (int h = 0; h < 8; h++) v0 += g_Apart[(h * D_ + d) * C_ + tid];

    float v1 = __int_as_float(0xff800000);
    if (tid < C_ - 256) {
        v1 = 0.f;
#pragma unroll
        for (int h = 0; h < 8; h++) v1 += g_Apart[(h * D_ + d) * C_ + 256 + tid];
    }

    s_red[tid] = fmaxf(v0, v1);
    __syncthreads();
    for (int s = 128; s > 0; s >>= 1) {
        if (tid < s) s_red[tid] = fmaxf(s_red[tid], s_red[tid + s]);
        __syncthreads();
    }
    float mx = s_red[0];
    __syncthreads();

    float e0 = expf(v0 - mx);
    float e1 = (tid < C_ - 256) ? expf(v1 - mx) : 0.f;
    s_red[tid] = e0 + e1;
    __syncthreads();
    for (int s = 128; s > 0; s >>= 1) {
        if (tid < s) s_red[tid] += s_red[tid + s];
        __syncthreads();
    }
    float inv = 1.f / s_red[0];

    float w0 = e0 * inv;
    __half h0 = __float2half_rn(w0);
    g_Wh[d * CP + tid] = h0;
    g_Wl[d * CP + tid] = __float2half_rn(w0 - __half2float(h0));
    if (tid < C_ - 256) {
        float w1 = e1 * inv;
        __half h1 = __float2half_rn(w1);
        g_Wh[d * CP + 256 + tid] = h1;
        g_Wl[d * CP + 256 + tid] = __float2half_rn(w1 - __half2float(h1));
    }
}

// ---------------------------------------------------------------------------
// Stage 4: out[b,d,t] = sum_c w[d,c] * X[b,c,t] via mma.sync fp16, 2 passes:
// Wh*Xf + Wl*Xf (W split to fp16 hi/lo, X single fp16).
// CTA: 96d x 128t, K chunks of 32 c (9 chunks), double-buffered smem,
// one __syncthreads per chunk. Warps 2(d) x 4(t), warp tile 48d x 32t.
// ---------------------------------------------------------------------------
#define ASTRIDE 80
#define BSTRIDE 272
#define OFF_AH  0
#define OFF_AL  7680
#define OFF_BH  15360
#define BUFSZ   24064
#define SMEM_TOTAL (2 * BUFSZ)

__global__ __launch_bounds__(256, 2) void bdt_mma_kernel(const float* __restrict__ X,
                                                         float* __restrict__ out) {
    extern __shared__ __align__(16) uint8_t smem[];

    int tid  = threadIdx.x;
    int wid  = tid >> 5;
    int lane = tid & 31;
    int d0   = blockIdx.x * 96;
    int t0   = blockIdx.y * 128;
    int b    = blockIdx.z;
    int wd   = wid >> 2;       // 0..1
    int wt   = wid & 3;        // 0..3

    float acc[3][4][4];
#pragma unroll
    for (int m = 0; m < 3; m++)
#pragma unroll
        for (int n = 0; n < 4; n++)
#pragma unroll
            for (int k = 0; k < 4; k++) acc[m][n][k] = 0.f;

    uint32_t sbase = smem_u32(smem);
    uint32_t laA = (uint32_t)((lane & 15) * ASTRIDE + (lane >> 4) * 16);
    uint32_t laB = (uint32_t)((lane & 15) * BSTRIDE + (lane >> 4) * 16);

    // X staging mapping: thread -> (c = pc, t = pt..pt+15)
    int pc = tid >> 3;             // 0..31
    int pt = (tid & 7) * 16;       // 0..112
    const float* Xbase = X + (size_t)b * C_ * T_ + t0 + pt;

    float4 xv[4];

    // ---------- helpers ----------
    auto stsX = [&](uint8_t* buf) {
        uint32_t h[8];
#pragma unroll
        for (int j = 0; j < 4; j++) {
            __half2 p0 = __floats2half2_rn(xv[j].x, xv[j].y);
            __half2 p1 = __floats2half2_rn(xv[j].z, xv[j].w);
            h[2 * j]     = *(uint32_t*)&p0;
            h[2 * j + 1] = *(uint32_t*)&p1;
        }
        uint32_t off = (uint32_t)(pc * BSTRIDE + pt * 2);
        *(uint4*)(buf + OFF_BH + off)      = make_uint4(h[0], h[1], h[2], h[3]);
        *(uint4*)(buf + OFF_BH + off + 16) = make_uint4(h[4], h[5], h[6], h[7]);
    };
    auto stageW = [&](uint8_t* buf, int c0n, int ncn) {
#pragma unroll
        for (int k = 0; k < 3; k++) {
            int i = tid + k * 256;          // 0..767
            int half = (i >= 384);
            int j = half ? i - 384 : i;     // 0..383
            int row = j >> 2, seg = j & 3;
            if (seg * 8 < ncn) {
                int src = (d0 + row) * CP + c0n + seg * 8;
                uint4 v = half ? *(const uint4*)&g_Wl[src] : *(const uint4*)&g_Wh[src];
                *(uint4*)(buf + (half ? OFF_AL : OFF_AH) + (uint32_t)(row * ASTRIDE + seg * 16)) = v;
            }
        }
    };

    // ---------- prologue: stage chunk 0, prefetch chunk 1 ----------
#pragma unroll
    for (int j = 0; j < 4; j++)
        xv[j] = *(const float4*)(Xbase + (size_t)pc * T_ + j * 4);
    stsX(smem);
    stageW(smem, 0, 32);
#pragma unroll
    for (int j = 0; j < 4; j++)
        xv[j] = *(const float4*)(Xbase + (size_t)(32 + pc) * T_ + j * 4);
    __syncthreads();

    // ---------- main loop: one sync per chunk ----------
    for (int ch = 0; ch < 9; ch++) {
        int cur = ch & 1;
        uint32_t bufo = (uint32_t)cur * BUFSZ;
        int nc = (ch == 8) ? 16 : 32;

        // stage chunk ch+1 into the other buffer (overlaps MMA of chunk ch)
        if (ch < 8) {
            int ncn = (ch == 7) ? 16 : 32;
            uint8_t* nbuf = smem + (uint32_t)(cur ^ 1) * BUFSZ;
            if (pc < ncn) stsX(nbuf);
            stageW(nbuf, (ch + 1) * 32, ncn);
            if (ch < 7) {
                int nc2 = (ch == 6) ? 16 : 32;
                if (pc < nc2) {
#pragma unroll
                    for (int j = 0; j < 4; j++)
                        xv[j] = *(const float4*)(Xbase + (size_t)((ch + 2) * 32 + pc) * T_ + j * 4);
                }
            }
        }

        // ---- mma on buf[cur] ----
        uint32_t Ah = sbase + bufo + OFF_AH + (uint32_t)(wd * 48 * ASTRIDE) + laA;
        uint32_t Al = sbase + bufo + OFF_AL + (uint32_t)(wd * 48 * ASTRIDE) + laA;
        uint32_t Bh = sbase + bufo + OFF_BH + (uint32_t)(wt * 64) + laB;

        int nks = nc >> 4;
        for (int ks = 0; ks < nks; ks++) {
            uint32_t ao = (uint32_t)(ks * 32);
            uint32_t bo = (uint32_t)(ks * 16 * BSTRIDE);

            uint32_t ah[3][4], al[3][4];
#pragma unroll
            for (int mt = 0; mt < 3; mt++) {
                LDSM_X4(ah[mt], Ah + (uint32_t)(mt * 16 * ASTRIDE) + ao);
                LDSM_X4(al[mt], Al + (uint32_t)(mt * 16 * ASTRIDE) + ao);
            }
            uint32_t bh[8];
            LDSM_X4_T(bh,     Bh + bo);
            LDSM_X4_T(bh + 4, Bh + bo + 32);

#pragma unroll
            for (int mt = 0; mt < 3; mt++) {
#pragma unroll
                for (int nt = 0; nt < 4; nt++) {
                    MMA16816F(acc[mt][nt], ah[mt], bh[2 * nt], bh[2 * nt + 1]);
                    MMA16816F(acc[mt][nt], al[mt], bh[2 * nt], bh[2 * nt + 1]);
                }
            }
        }
        __syncthreads();
    }

    // ---- epilogue: fragment rows = d, cols = t ----
#pragma unroll
    for (int mt = 0; mt < 3; mt++) {
        int dr = d0 + wd * 48 + mt * 16 + (lane >> 2);
#pragma unroll
        for (int nt = 0; nt < 4; nt++) {
            int tt = t0 + wt * 32 + nt * 8 + (lane & 3) * 2;
            if (dr < D_)
                *(float2*)(out + ((size_t)b * D_ + dr) * T_ + tt) =
                    make_float2(acc[mt][nt][0], acc[mt][nt][1]);
            if (dr + 8 < D_)
                *(float2*)(out + ((size_t)b * D_ + dr + 8) * T_ + tt) =
                    make_float2(acc[mt][nt][2], acc[mt][nt][3]);
        }
    }
}

// ---------------------------------------------------------------------------
extern "C" void kernel_launch(void* const* d_in, const int* in_sizes, int n_in,
                              void* d_out, int out_size) {
    const float* X   = (const float*)d_in[0];
    const float* loc = (const float*)d_in[1];
    const float* zre = (const float*)d_in[2];
    const float* zim = (const float*)d_in[3];
    float* out = (float*)d_out;

    cudaFuncSetAttribute(bdt_mma_kernel, cudaFuncAttributeMaxDynamicSharedMemorySize, SMEM_TOTAL);

    trig_kernel<<<KK_, C_>>>(loc);
    a_kernel<<<dim3(17, 8), 272>>>(zre, zim);
    softmax_kernel<<<D_, 256>>>();
    bdt_mma_kernel<<<dim3(3, 8, B_), 256, SMEM_TOTAL>>>(X, out);
}

// round 10
// speedup vs baseline: 1.9915x; 1.2566x over previous
#include <cuda_runtime.h>
#include <cuda_fp16.h>
#include <cstdint>
#include <math.h>

#define B_   128
#define C_   272
#define T_   1024
#define D_   270
#define KK_  1024
#define DP   288      // padded d rows for W (3 x 96)
#define CP   320      // padded c cols for W
#define NCHUNK 16

// Scratch (device globals; allocation-free contract). Zero-initialized.
__device__ float g_cosP[KK_ * C_];
__device__ float g_sinP[KK_ * C_];
__device__ float g_Apart[NCHUNK * D_ * C_];
__device__ __half g_Wh[DP * CP];   // softmax weights (fp16), [d][c], zero-padded

__device__ __forceinline__ uint32_t smem_u32(const void* p) {
    uint32_t a;
    asm("{ .reg .u64 t; cvta.to.shared.u64 t, %1; cvt.u32.u64 %0, t; }" : "=r"(a) : "l"(p));
    return a;
}

#define LDSM_X4(r, a)                                                        \
    asm volatile("ldmatrix.sync.aligned.m8n8.x4.shared.b16 {%0,%1,%2,%3}, [%4];" \
        : "=r"((r)[0]), "=r"((r)[1]), "=r"((r)[2]), "=r"((r)[3]) : "r"(a))
#define LDSM_X4_T(r, a)                                                      \
    asm volatile("ldmatrix.sync.aligned.m8n8.x4.trans.shared.b16 {%0,%1,%2,%3}, [%4];" \
        : "=r"((r)[0]), "=r"((r)[1]), "=r"((r)[2]), "=r"((r)[3]) : "r"(a))

#define MMA16816F(d, a, b0v, b1v)                                            \
    asm volatile("mma.sync.aligned.m16n8k16.row.col.f32.f16.f16.f32 "        \
        "{%0,%1,%2,%3}, {%4,%5,%6,%7}, {%8,%9}, {%0,%1,%2,%3};"              \
        : "+f"((d)[0]), "+f"((d)[1]), "+f"((d)[2]), "+f"((d)[3])             \
        : "r"((a)[0]), "r"((a)[1]), "r"((a)[2]), "r"((a)[3]),                \
          "r"(b0v), "r"(b1v))

// ---------------------------------------------------------------------------
// Stage 1: trig table (reference-exact f32 phase, correctly-rounded cos/sin).
// ---------------------------------------------------------------------------
__global__ void trig_kernel(const float* __restrict__ loc) {
    int kl = blockIdx.x;
    int c  = threadIdx.x;
    float x = loc[2 * c];
    float y = loc[2 * c + 1];
    float kf = (float)(kl >> 5);
    float lf = (float)(kl & 31);
    float s = __fadd_rn(__fmul_rn(kf, x), __fmul_rn(lf, y));
    float p = __fmul_rn(6.28318530717958647692f, s);
    double sd, cd;
    sincos((double)p, &sd, &cd);
    g_cosP[kl * C_ + c] = (float)cd;
    g_sinP[kl * C_ + c] = (float)sd;
}

// ---------------------------------------------------------------------------
// Stage 2: A[d,c] partials (deterministic, per-kl-chunk buffers).
// Grid (17 d-tiles, 16 kl-chunks of 64), 272 threads (= c).
// ---------------------------------------------------------------------------
__global__ void a_kernel(const float* __restrict__ zre, const float* __restrict__ zim) {
    __shared__ float s_zre[16][64];
    __shared__ float s_zim[16][64];
    int d0  = blockIdx.x * 16;
    int kl0 = blockIdx.y * 64;
    int tid = threadIdx.x;

    for (int i = tid; i < 16 * 64; i += 272) {
        int dd = i >> 6, j = i & 63;
        int d = d0 + dd;
        float vr = 0.f, vi = 0.f;
        if (d < D_) {
            vr = zre[d * KK_ + kl0 + j];
            vi = zim[d * KK_ + kl0 + j];
        }
        s_zre[dd][j] = vr;
        s_zim[dd][j] = vi;
    }
    __syncthreads();

    int c = tid;
    float acc[16];
#pragma unroll
    for (int i = 0; i < 16; i++) acc[i] = 0.f;

    for (int j = 0; j < 64; j++) {
        float cv = g_cosP[(kl0 + j) * C_ + c];
        float sv = g_sinP[(kl0 + j) * C_ + c];
#pragma unroll
        for (int i = 0; i < 16; i++)
            acc[i] = fmaf(s_zre[i][j], cv, fmaf(s_zim[i][j], sv, acc[i]));
    }

#pragma unroll
    for (int i = 0; i < 16; i++) {
        int d = d0 + i;
        if (d < D_)
            g_Apart[(blockIdx.y * D_ + d) * C_ + c] = acc[i];
    }
}

// ---------------------------------------------------------------------------
// Stage 3: softmax over c per row d; emit fp16 weights [d][c].
// ---------------------------------------------------------------------------
__global__ void softmax_kernel() {
    int d   = blockIdx.x;
    int tid = threadIdx.x;   // 256
    __shared__ float s_red[256];

    float v0 = 0.f;
#pragma unroll
    for (int h = 0; h < NCHUNK; h++) v0 += g_Apart[(h * D_ + d) * C_ + tid];

    float v1 = __int_as_float(0xff800000);
    if (tid < C_ - 256) {
        v1 = 0.f;
#pragma unroll
        for (int h = 0; h < NCHUNK; h++) v1 += g_Apart[(h * D_ + d) * C_ + 256 + tid];
    }

    s_red[tid] = fmaxf(v0, v1);
    __syncthreads();
    for (int s = 128; s > 0; s >>= 1) {
        if (tid < s) s_red[tid] = fmaxf(s_red[tid], s_red[tid + s]);
        __syncthreads();
    }
    float mx = s_red[0];
    __syncthreads();

    float e0 = expf(v0 - mx);
    float e1 = (tid < C_ - 256) ? expf(v1 - mx) : 0.f;
    s_red[tid] = e0 + e1;
    __syncthreads();
    for (int s = 128; s > 0; s >>= 1) {
        if (tid < s) s_red[tid] += s_red[tid + s];
        __syncthreads();
    }
    float inv = 1.f / s_red[0];

    g_Wh[d * CP + tid] = __float2half_rn(e0 * inv);
    if (tid < C_ - 256)
        g_Wh[d * CP + 256 + tid] = __float2half_rn(e1 * inv);
}

// ---------------------------------------------------------------------------
// Stage 4: out[b,d,t] = sum_c w[d,c] * X[b,c,t] via mma.sync fp16, 1 pass.
// CTA: 96d x 128t, K chunks of 32 c (9 chunks), double-buffered smem,
// one __syncthreads per chunk. Warps 2(d) x 4(t), warp tile 48d x 32t.
// ---------------------------------------------------------------------------
#define ASTRIDE 80
#define BSTRIDE 272
#define OFF_AH  0
#define OFF_BH  7680
#define BUFSZ   16384
#define SMEM_TOTAL (2 * BUFSZ)

__global__ __launch_bounds__(256, 2) void bdt_mma_kernel(const float* __restrict__ X,
                                                         float* __restrict__ out) {
    extern __shared__ __align__(16) uint8_t smem[];

    int tid  = threadIdx.x;
    int wid  = tid >> 5;
    int lane = tid & 31;
    int d0   = blockIdx.x * 96;
    int t0   = blockIdx.y * 128;
    int b    = blockIdx.z;
    int wd   = wid >> 2;       // 0..1
    int wt   = wid & 3;        // 0..3

    float acc[3][4][4];
#pragma unroll
    for (int m = 0; m < 3; m++)
#pragma unroll
        for (int n = 0; n < 4; n++)
#pragma unroll
            for (int k = 0; k < 4; k++) acc[m][n][k] = 0.f;

    uint32_t sbase = smem_u32(smem);
    uint32_t laA = (uint32_t)((lane & 15) * ASTRIDE + (lane >> 4) * 16);
    uint32_t laB = (uint32_t)((lane & 15) * BSTRIDE + (lane >> 4) * 16);

    // X staging mapping: thread -> (c = pc, t = pt..pt+15)
    int pc = tid >> 3;             // 0..31
    int pt = (tid & 7) * 16;       // 0..112
    const float* Xbase = X + (size_t)b * C_ * T_ + t0 + pt;

    float4 xv[4];

    // ---------- helpers ----------
    auto stsX = [&](uint8_t* buf) {
        uint32_t h[8];
#pragma unroll
        for (int j = 0; j < 4; j++) {
            __half2 p0 = __floats2half2_rn(xv[j].x, xv[j].y);
            __half2 p1 = __floats2half2_rn(xv[j].z, xv[j].w);
            h[2 * j]     = *(uint32_t*)&p0;
            h[2 * j + 1] = *(uint32_t*)&p1;
        }
        uint32_t off = (uint32_t)(pc * BSTRIDE + pt * 2);
        *(uint4*)(buf + OFF_BH + off)      = make_uint4(h[0], h[1], h[2], h[3]);
        *(uint4*)(buf + OFF_BH + off + 16) = make_uint4(h[4], h[5], h[6], h[7]);
    };
    auto stageW = [&](uint8_t* buf, int c0n, int ncn) {
#pragma unroll
        for (int k = 0; k < 2; k++) {
            int i = tid + k * 256;          // 0..511, need 0..383
            if (i < 384) {
                int row = i >> 2, seg = i & 3;
                if (seg * 8 < ncn) {
                    int src = (d0 + row) * CP + c0n + seg * 8;
                    uint4 v = *(const uint4*)&g_Wh[src];
                    *(uint4*)(buf + OFF_AH + (uint32_t)(row * ASTRIDE + seg * 16)) = v;
                }
            }
        }
    };

    // ---------- prologue: stage chunk 0, prefetch chunk 1 ----------
#pragma unroll
    for (int j = 0; j < 4; j++)
        xv[j] = *(const float4*)(Xbase + (size_t)pc * T_ + j * 4);
    stsX(smem);
    stageW(smem, 0, 32);
#pragma unroll
    for (int j = 0; j < 4; j++)
        xv[j] = *(const float4*)(Xbase + (size_t)(32 + pc) * T_ + j * 4);
    __syncthreads();

    // ---------- main loop: one sync per chunk ----------
    for (int ch = 0; ch < 9; ch++) {
        int cur = ch & 1;
        uint32_t bufo = (uint32_t)cur * BUFSZ;
        int nc = (ch == 8) ? 16 : 32;

        // stage chunk ch+1 into the other buffer (overlaps MMA of chunk ch)
        if (ch < 8) {
            int ncn = (ch == 7) ? 16 : 32;
            uint8_t* nbuf = smem + (uint32_t)(cur ^ 1) * BUFSZ;
            if (pc < ncn) stsX(nbuf);
            stageW(nbuf, (ch + 1) * 32, ncn);
            if (ch < 7) {
                int nc2 = (ch == 6) ? 16 : 32;
                if (pc < nc2) {
#pragma unroll
                    for (int j = 0; j < 4; j++)
                        xv[j] = *(const float4*)(Xbase + (size_t)((ch + 2) * 32 + pc) * T_ + j * 4);
                }
            }
        }

        // ---- mma on buf[cur] ----
        uint32_t Ah = sbase + bufo + OFF_AH + (uint32_t)(wd * 48 * ASTRIDE) + laA;
        uint32_t Bh = sbase + bufo + OFF_BH + (uint32_t)(wt * 64) + laB;

        int nks = nc >> 4;
        for (int ks = 0; ks < nks; ks++) {
            uint32_t ao = (uint32_t)(ks * 32);
            uint32_t bo = (uint32_t)(ks * 16 * BSTRIDE);

            uint32_t ah[3][4];
#pragma unroll
            for (int mt = 0; mt < 3; mt++)
                LDSM_X4(ah[mt], Ah + (uint32_t)(mt * 16 * ASTRIDE) + ao);
            uint32_t bh[8];
            LDSM_X4_T(bh,     Bh + bo);
            LDSM_X4_T(bh + 4, Bh + bo + 32);

#pragma unroll
            for (int mt = 0; mt < 3; mt++) {
#pragma unroll
                for (int nt = 0; nt < 4; nt++)
                    MMA16816F(acc[mt][nt], ah[mt], bh[2 * nt], bh[2 * nt + 1]);
            }
        }
        __syncthreads();
    }

    // ---- epilogue: fragment rows = d, cols = t ----
#pragma unroll
    for (int mt = 0; mt < 3; mt++) {
        int dr = d0 + wd * 48 + mt * 16 + (lane >> 2);
#pragma unroll
        for (int nt = 0; nt < 4; nt++) {
            int tt = t0 + wt * 32 + nt * 8 + (lane & 3) * 2;
            if (dr < D_)
                *(float2*)(out + ((size_t)b * D_ + dr) * T_ + tt) =
                    make_float2(acc[mt][nt][0], acc[mt][nt][1]);
            if (dr + 8 < D_)
                *(float2*)(out + ((size_t)b * D_ + dr + 8) * T_ + tt) =
                    make_float2(acc[mt][nt][2], acc[mt][nt][3]);
        }
    }
}

// ---------------------------------------------------------------------------
extern "C" void kernel_launch(void* const* d_in, const int* in_sizes, int n_in,
                              void* d_out, int out_size) {
    const float* X   = (const float*)d_in[0];
    const float* loc = (const float*)d_in[1];
    const float* zre = (const float*)d_in[2];
    const float* zim = (const float*)d_in[3];
    float* out = (float*)d_out;

    cudaFuncSetAttribute(bdt_mma_kernel, cudaFuncAttributeMaxDynamicSharedMemorySize, SMEM_TOTAL);

    trig_kernel<<<KK_, C_>>>(loc);
    a_kernel<<<dim3(17, NCHUNK), 272>>>(zre, zim);
    softmax_kernel<<<D_, 256>>>();
    bdt_mma_kernel<<<dim3(3, 8, B_), 256, SMEM_TOTAL>>>(X, out);
}

// round 12
// speedup vs baseline: 2.1868x; 1.0980x over previous
#include <cuda_runtime.h>
#include <cuda_fp16.h>
#include <cstdint>
#include <math.h>

#define B_   128
#define C_   272
#define T_   1024
#define D_   270
#define KK_  1024
#define DP   288      // padded d rows for W (3 x 96)
#define CP   320      // padded c cols for W
#define NCHUNK 16
#define NMT  18       // 288/16 d-fragment tiles
#define NKS  17       // 272/16 k-steps

// Scratch (device globals; allocation-free contract). Zero-initialized.
__device__ float g_cosP[KK_ * C_];
__device__ float g_sinP[KK_ * C_];
__device__ float g_Apart[NCHUNK * D_ * C_];
__device__ __half g_Wh[DP * CP];              // softmax weights fp16, [d][c], zero-padded
__device__ uint4  g_Wfrag[NMT * NKS * 32];    // W in m16n8k16 A-fragment layout

__device__ __forceinline__ uint32_t smem_u32(const void* p) {
    uint32_t a;
    asm("{ .reg .u64 t; cvta.to.shared.u64 t, %1; cvt.u32.u64 %0, t; }" : "=r"(a) : "l"(p));
    return a;
}

#define LDSM_X4_T(r, a)                                                      \
    asm volatile("ldmatrix.sync.aligned.m8n8.x4.trans.shared.b16 {%0,%1,%2,%3}, [%4];" \
        : "=r"((r)[0]), "=r"((r)[1]), "=r"((r)[2]), "=r"((r)[3]) : "r"(a))

#define MMA16816F(d, a, b0v, b1v)                                            \
    asm volatile("mma.sync.aligned.m16n8k16.row.col.f32.f16.f16.f32 "        \
        "{%0,%1,%2,%3}, {%4,%5,%6,%7}, {%8,%9}, {%0,%1,%2,%3};"              \
        : "+f"((d)[0]), "+f"((d)[1]), "+f"((d)[2]), "+f"((d)[3])             \
        : "r"((a)[0]), "r"((a)[1]), "r"((a)[2]), "r"((a)[3]),                \
          "r"(b0v), "r"(b1v))

// ---------------------------------------------------------------------------
// Stage 1: trig table (reference-exact f32 phase; sincosf = 2-ulp, error
// buried under the fp16 GEMM floor).
// ---------------------------------------------------------------------------
__global__ void trig_kernel(const float* __restrict__ loc) {
    int kl = blockIdx.x;
    int c  = threadIdx.x;
    float x = loc[2 * c];
    float y = loc[2 * c + 1];
    float kf = (float)(kl >> 5);
    float lf = (float)(kl & 31);
    float s = __fadd_rn(__fmul_rn(kf, x), __fmul_rn(lf, y));
    float p = __fmul_rn(6.28318530717958647692f, s);
    float sd, cd;
    sincosf(p, &sd, &cd);
    g_cosP[kl * C_ + c] = cd;
    g_sinP[kl * C_ + c] = sd;
}

// ---------------------------------------------------------------------------
// Stage 2: A[d,c] partials (deterministic, per-kl-chunk buffers).
// Grid (17 d-tiles, 16 kl-chunks of 64), 272 threads (= c).
// ---------------------------------------------------------------------------
__global__ void a_kernel(const float* __restrict__ zre, const float* __restrict__ zim) {
    __shared__ float s_zre[16][64];
    __shared__ float s_zim[16][64];
    int d0  = blockIdx.x * 16;
    int kl0 = blockIdx.y * 64;
    int tid = threadIdx.x;

    for (int i = tid; i < 16 * 64; i += 272) {
        int dd = i >> 6, j = i & 63;
        int d = d0 + dd;
        float vr = 0.f, vi = 0.f;
        if (d < D_) {
            vr = zre[d * KK_ + kl0 + j];
            vi = zim[d * KK_ + kl0 + j];
        }
        s_zre[dd][j] = vr;
        s_zim[dd][j] = vi;
    }
    __syncthreads();

    int c = tid;
    float acc[16];
#pragma unroll
    for (int i = 0; i < 16; i++) acc[i] = 0.f;

    for (int j = 0; j < 64; j++) {
        float cv = g_cosP[(kl0 + j) * C_ + c];
        float sv = g_sinP[(kl0 + j) * C_ + c];
#pragma unroll
        for (int i = 0; i < 16; i++)
            acc[i] = fmaf(s_zre[i][j], cv, fmaf(s_zim[i][j], sv, acc[i]));
    }

#pragma unroll
    for (int i = 0; i < 16; i++) {
        int d = d0 + i;
        if (d < D_)
            g_Apart[(blockIdx.y * D_ + d) * C_ + c] = acc[i];
    }
}

// ---------------------------------------------------------------------------
// Stage 3: softmax over c per row d; emit fp16 weights [d][c].
// ---------------------------------------------------------------------------
__global__ void softmax_kernel() {
    int d   = blockIdx.x;
    int tid = threadIdx.x;   // 256
    __shared__ float s_red[256];

    float v0 = 0.f;
#pragma unroll
    for (int h = 0; h < NCHUNK; h++) v0 += g_Apart[(h * D_ + d) * C_ + tid];

    float v1 = __int_as_float(0xff800000);
    if (tid < C_ - 256) {
        v1 = 0.f;
#pragma unroll
        for (int h = 0; h < NCHUNK; h++) v1 += g_Apart[(h * D_ + d) * C_ + 256 + tid];
    }

    s_red[tid] = fmaxf(v0, v1);
    __syncthreads();
    for (int s = 128; s > 0; s >>= 1) {
        if (tid < s) s_red[tid] = fmaxf(s_red[tid], s_red[tid + s]);
        __syncthreads();
    }
    float mx = s_red[0];
    __syncthreads();

    float e0 = expf(v0 - mx);
    float e1 = (tid < C_ - 256) ? expf(v1 - mx) : 0.f;
    s_red[tid] = e0 + e1;
    __syncthreads();
    for (int s = 128; s > 0; s >>= 1) {
        if (tid < s) s_red[tid] += s_red[tid + s];
        __syncthreads();
    }
    float inv = 1.f / s_red[0];

    g_Wh[d * CP + tid] = __float2half_rn(e0 * inv);
    if (tid < C_ - 256)
        g_Wh[d * CP + 256 + tid] = __float2half_rn(e1 * inv);
}

// ---------------------------------------------------------------------------
// Stage 3b: repack W into m16n8k16 A-fragment layout.
// Fragment reg r for lane L of tile (mt, ks):
//   r0 = W[d, c], W[d, c+1]   with d = mt*16 + L/4, c = ks*16 + (L%4)*2
//   r1 = d+8; r2 = c+8; r3 = d+8, c+8.
// ---------------------------------------------------------------------------
__global__ void repack_kernel() {
    int mt   = blockIdx.x;    // 0..17
    int ks   = blockIdx.y;    // 0..16
    int lane = threadIdx.x;   // 0..31
    int d = mt * 16 + (lane >> 2);
    int c = ks * 16 + (lane & 3) * 2;
    uint32_t r0 = *(const uint32_t*)&g_Wh[d * CP + c];
    uint32_t r1 = *(const uint32_t*)&g_Wh[(d + 8) * CP + c];
    uint32_t r2 = *(const uint32_t*)&g_Wh[d * CP + c + 8];
    uint32_t r3 = *(const uint32_t*)&g_Wh[(d + 8) * CP + c + 8];
    g_Wfrag[(mt * NKS + ks) * 32 + lane] = make_uint4(r0, r1, r2, r3);
}

// ---------------------------------------------------------------------------
// Stage 4: out[b,d,t] = sum_c w[d,c] * X[b,c,t] via mma.sync fp16.
// A fragments come straight from g_Wfrag via LDG.128 (no smem for W).
// B (X tile) staged fp16 in double-buffered smem, one sync per chunk.
// CTA: 96d x 128t, warps 2(d) x 4(t), warp tile 48d x 32t.
// ---------------------------------------------------------------------------
#define BSTRIDE 272
#define BUFSZ   8704
#define SMEM_TOTAL (2 * BUFSZ)

__global__ __launch_bounds__(256, 2) void bdt_mma_kernel(const float* __restrict__ X,
                                                         float* __restrict__ out) {
    extern __shared__ __align__(16) uint8_t smem[];

    int tid  = threadIdx.x;
    int wid  = tid >> 5;
    int lane = tid & 31;
    int d0   = blockIdx.x * 96;
    int t0   = blockIdx.y * 128;
    int b    = blockIdx.z;
    int wd   = wid >> 2;       // 0..1
    int wt   = wid & 3;        // 0..3

    float acc[3][4][4];
#pragma unroll
    for (int m = 0; m < 3; m++)
#pragma unroll
        for (int n = 0; n < 4; n++)
#pragma unroll
            for (int k = 0; k < 4; k++) acc[m][n][k] = 0.f;

    uint32_t sbase = smem_u32(smem);
    uint32_t laB = (uint32_t)((lane & 15) * BSTRIDE + (lane >> 4) * 16);

    // A-fragment base: warp covers mtiles (bx*6 + wd*3 + {0,1,2})
    const uint4* wfrag = g_Wfrag + (size_t)((blockIdx.x * 6 + wd * 3) * NKS) * 32 + lane;

    // X staging mapping: thread -> (c = pc, t = pt..pt+15)
    int pc = tid >> 3;             // 0..31
    int pt = (tid & 7) * 16;       // 0..112
    const float* Xbase = X + (size_t)b * C_ * T_ + t0 + pt;

    float4 xv[4];

    auto stsX = [&](uint8_t* buf) {
        uint32_t h[8];
#pragma unroll
        for (int j = 0; j < 4; j++) {
            __half2 p0 = __floats2half2_rn(xv[j].x, xv[j].y);
            __half2 p1 = __floats2half2_rn(xv[j].z, xv[j].w);
            h[2 * j]     = *(uint32_t*)&p0;
            h[2 * j + 1] = *(uint32_t*)&p1;
        }
        uint32_t off = (uint32_t)(pc * BSTRIDE + pt * 2);
        *(uint4*)(buf + off)      = make_uint4(h[0], h[1], h[2], h[3]);
        *(uint4*)(buf + off + 16) = make_uint4(h[4], h[5], h[6], h[7]);
    };

    // ---------- prologue: stage chunk 0, prefetch chunk 1 ----------
#pragma unroll
    for (int j = 0; j < 4; j++)
        xv[j] = *(const float4*)(Xbase + (size_t)pc * T_ + j * 4);
    stsX(smem);
#pragma unroll
    for (int j = 0; j < 4; j++)
        xv[j] = *(const float4*)(Xbase + (size_t)(32 + pc) * T_ + j * 4);
    __syncthreads();

    // ---------- main loop: one sync per chunk ----------
    for (int ch = 0; ch < 9; ch++) {
        int cur = ch & 1;
        uint32_t bufo = (uint32_t)cur * BUFSZ;
        int nc = (ch == 8) ? 16 : 32;
        int nks = nc >> 4;

        // prefetch A fragments for this chunk (L1/L2-hot, issued early)
        uint4 af[2][3];
#pragma unroll
        for (int ks = 0; ks < 2; ks++) {
            if (ks < nks) {
#pragma unroll
                for (int mt = 0; mt < 3; mt++)
                    af[ks][mt] = __ldg(wfrag + ((size_t)mt * NKS + (ch * 2 + ks)) * 32);
            }
        }

        // stage chunk ch+1 into the other buffer (overlaps MMA of chunk ch)
        if (ch < 8) {
            int ncn = (ch == 7) ? 16 : 32;
            uint8_t* nbuf = smem + (uint32_t)(cur ^ 1) * BUFSZ;
            if (pc < ncn) stsX(nbuf);
            if (ch < 7) {
                int nc2 = (ch == 6) ? 16 : 32;
                if (pc < nc2) {
#pragma unroll
                    for (int j = 0; j < 4; j++)
                        xv[j] = *(const float4*)(Xbase + (size_t)((ch + 2) * 32 + pc) * T_ + j * 4);
                }
            }
        }

        // ---- mma on buf[cur] ----
        uint32_t Bh = sbase + bufo + (uint32_t)(wt * 64) + laB;

        for (int ks = 0; ks < nks; ks++) {
            uint32_t bo = (uint32_t)(ks * 16 * BSTRIDE);
            uint32_t bh[8];
            LDSM_X4_T(bh,     Bh + bo);
            LDSM_X4_T(bh + 4, Bh + bo + 32);

#pragma unroll
            for (int mt = 0; mt < 3; mt++) {
                uint32_t ah[4] = {af[ks][mt].x, af[ks][mt].y, af[ks][mt].z, af[ks][mt].w};
#pragma unroll
                for (int nt = 0; nt < 4; nt++)
                    MMA16816F(acc[mt][nt], ah, bh[2 * nt], bh[2 * nt + 1]);
            }
        }
        __syncthreads();
    }

    // ---- epilogue: fragment rows = d, cols = t ----
#pragma unroll
    for (int mt = 0; mt < 3; mt++) {
        int dr = d0 + wd * 48 + mt * 16 + (lane >> 2);
#pragma unroll
        for (int nt = 0; nt < 4; nt++) {
            int tt = t0 + wt * 32 + nt * 8 + (lane & 3) * 2;
            if (dr < D_)
                *(float2*)(out + ((size_t)b * D_ + dr) * T_ + tt) =
                    make_float2(acc[mt][nt][0], acc[mt][nt][1]);
            if (dr + 8 < D_)
                *(float2*)(out + ((size_t)b * D_ + dr + 8) * T_ + tt) =
                    make_float2(acc[mt][nt][2], acc[mt][nt][3]);
        }
    }
}

// ---------------------------------------------------------------------------
extern "C" void kernel_launch(void* const* d_in, const int* in_sizes, int n_in,
                              void* d_out, int out_size) {
    const float* X   = (const float*)d_in[0];
    const float* loc = (const float*)d_in[1];
    const float* zre = (const float*)d_in[2];
    const float* zim = (const float*)d_in[3];
    float* out = (float*)d_out;

    cudaFuncSetAttribute(bdt_mma_kernel, cudaFuncAttributeMaxDynamicSharedMemorySize, SMEM_TOTAL);

    trig_kernel<<<KK_, C_>>>(loc);
    a_kernel<<<dim3(17, NCHUNK), 272>>>(zre, zim);
    softmax_kernel<<<D_, 256>>>();
    repack_kernel<<<dim3(NMT, NKS), 32>>>();
    bdt_mma_kernel<<<dim3(3, 8, B_), 256, SMEM_TOTAL>>>(X, out);
}

// round 15
// speedup vs baseline: 2.3183x; 1.0601x over previous
#include <cuda_runtime.h>
#include <cuda_fp16.h>
#include <cstdint>
#include <math.h>

#define B_   128
#define C_   272
#define T_   1024
#define D_   270
#define KK_  1024
#define NCHUNK 16
#define NMT  18       // 288/16 d-fragment tiles
#define NKS  17       // 272/16 k-steps

// Scratch (device globals; allocation-free contract). Zero-initialized.
__device__ float g_cosP[KK_ * C_];
__device__ float g_sinP[KK_ * C_];
__device__ float g_Apart[NCHUNK * D_ * C_];
__device__ uint4  g_Wfrag[NMT * NKS * 32];    // W in m16n8k16 A-fragment layout (fp16)

__device__ __forceinline__ uint32_t smem_u32(const void* p) {
    uint32_t a;
    asm("{ .reg .u64 t; cvta.to.shared.u64 t, %1; cvt.u32.u64 %0, t; }" : "=r"(a) : "l"(p));
    return a;
}

#define LDSM_X4_T(r, a)                                                      \
    asm volatile("ldmatrix.sync.aligned.m8n8.x4.trans.shared.b16 {%0,%1,%2,%3}, [%4];" \
        : "=r"((r)[0]), "=r"((r)[1]), "=r"((r)[2]), "=r"((r)[3]) : "r"(a))

#define MMA16816F(d, a, b0v, b1v)                                            \
    asm volatile("mma.sync.aligned.m16n8k16.row.col.f32.f16.f16.f32 "        \
        "{%0,%1,%2,%3}, {%4,%5,%6,%7}, {%8,%9}, {%0,%1,%2,%3};"              \
        : "+f"((d)[0]), "+f"((d)[1]), "+f"((d)[2]), "+f"((d)[3])             \
        : "r"((a)[0]), "r"((a)[1]), "r"((a)[2]), "r"((a)[3]),                \
          "r"(b0v), "r"(b1v))

// ---------------------------------------------------------------------------
// Stage 1: trig table (reference-exact f32 phase; sincosf 2-ulp, error
// buried under the fp16 GEMM floor).
// ---------------------------------------------------------------------------
__global__ void trig_kernel(const float* __restrict__ loc) {
    int kl = blockIdx.x;
    int c  = threadIdx.x;
    float x = loc[2 * c];
    float y = loc[2 * c + 1];
    float kf = (float)(kl >> 5);
    float lf = (float)(kl & 31);
    float s = __fadd_rn(__fmul_rn(kf, x), __fmul_rn(lf, y));
    float p = __fmul_rn(6.28318530717958647692f, s);
    float sd, cd;
    sincosf(p, &sd, &cd);
    g_cosP[kl * C_ + c] = cd;
    g_sinP[kl * C_ + c] = sd;
}

// ---------------------------------------------------------------------------
// Stage 2: A[d,c] partials (deterministic, per-kl-chunk buffers).
// Grid (17 d-tiles, 16 kl-chunks of 64), 272 threads (= c).
// ---------------------------------------------------------------------------
__global__ void a_kernel(const float* __restrict__ zre, const float* __restrict__ zim) {
    __shared__ float s_zre[16][64];
    __shared__ float s_zim[16][64];
    int d0  = blockIdx.x * 16;
    int kl0 = blockIdx.y * 64;
    int tid = threadIdx.x;

    for (int i = tid; i < 16 * 64; i += 272) {
        int dd = i >> 6, j = i & 63;
        int d = d0 + dd;
        float vr = 0.f, vi = 0.f;
        if (d < D_) {
            vr = zre[d * KK_ + kl0 + j];
            vi = zim[d * KK_ + kl0 + j];
        }
        s_zre[dd][j] = vr;
        s_zim[dd][j] = vi;
    }
    __syncthreads();

    int c = tid;
    float acc[16];
#pragma unroll
    for (int i = 0; i < 16; i++) acc[i] = 0.f;

    for (int j = 0; j < 64; j++) {
        float cv = g_cosP[(kl0 + j) * C_ + c];
        float sv = g_sinP[(kl0 + j) * C_ + c];
#pragma unroll
        for (int i = 0; i < 16; i++)
            acc[i] = fmaf(s_zre[i][j], cv, fmaf(s_zim[i][j], sv, acc[i]));
    }

#pragma unroll
    for (int i = 0; i < 16; i++) {
        int d = d0 + i;
        if (d < D_)
            g_Apart[(blockIdx.y * D_ + d) * C_ + c] = acc[i];
    }
}

// ---------------------------------------------------------------------------
// Stage 3: softmax over c per row d; scatter fp16 weights DIRECTLY into the
// m16n8k16 A-fragment layout (repack fused). Padding slots stay zero-init.
// Slot for (d, c): tile (mt=d/16, ks=c/16); dr=d%16, cr=c%16;
//   lane = (dr%8)*4 + (cr%8)/2; reg = (dr>=8) + 2*(cr>=8); half = cr%2.
// ---------------------------------------------------------------------------
__device__ __forceinline__ void scatter_w(int d, int c, float w) {
    int mt = d >> 4, ks = c >> 4, dr = d & 15, cr = c & 15;
    int lane = (dr & 7) * 4 + ((cr & 7) >> 1);
    int reg  = ((dr >> 3) & 1) + ((cr >> 3) & 1) * 2;
    __half* wf = (__half*)g_Wfrag;
    wf[(size_t)((mt * NKS + ks) * 32 + lane) * 8 + reg * 2 + (cr & 1)] = __float2half_rn(w);
}

__global__ void softmax_kernel() {
    int d   = blockIdx.x;
    int tid = threadIdx.x;   // 256
    __shared__ float s_red[256];

    float v0 = 0.f;
#pragma unroll
    for (int h = 0; h < NCHUNK; h++) v0 += g_Apart[(h * D_ + d) * C_ + tid];

    float v1 = __int_as_float(0xff800000);
    if (tid < C_ - 256) {
        v1 = 0.f;
#pragma unroll
        for (int h = 0; h < NCHUNK; h++) v1 += g_Apart[(h * D_ + d) * C_ + 256 + tid];
    }

    s_red[tid] = fmaxf(v0, v1);
    __syncthreads();
    for (int s = 128; s > 0; s >>= 1) {
        if (tid < s) s_red[tid] = fmaxf(s_red[tid], s_red[tid + s]);
        __syncthreads();
    }
    float mx = s_red[0];
    __syncthreads();

    float e0 = expf(v0 - mx);
    float e1 = (tid < C_ - 256) ? expf(v1 - mx) : 0.f;
    s_red[tid] = e0 + e1;
    __syncthreads();
    for (int s = 128; s > 0; s >>= 1) {
        if (tid < s) s_red[tid] += s_red[tid + s];
        __syncthreads();
    }
    float inv = 1.f / s_red[0];

    scatter_w(d, tid, e0 * inv);
    if (tid < C_ - 256) scatter_w(d, 256 + tid, e1 * inv);
}

// ---------------------------------------------------------------------------
// Stage 4: out[b,d,t] = sum_c w[d,c] * X[b,c,t] via mma.sync fp16.
// 128-thread CTA: 96d x 64t, warps 2(d) x 2(t), warp tile 48d x 32t.
// A fragments via LDG.128 from g_Wfrag (L1/L2-hot); B (X) staged fp16 in
// double-buffered static smem, one sync per chunk. 4+ CTAs/SM.
// ---------------------------------------------------------------------------
#define BSTRIDE 144           // 64t*2B + 16B pad (bank rotation 4/row)
#define BUFSZ   4608          // 32c * 144B

__global__ __launch_bounds__(128, 4) void bdt_mma_kernel(const float* __restrict__ X,
                                                         float* __restrict__ out) {
    __shared__ __align__(16) uint8_t smem[2 * BUFSZ];

    int tid  = threadIdx.x;
    int wid  = tid >> 5;
    int lane = tid & 31;
    int d0   = blockIdx.x * 96;
    int t0   = blockIdx.y * 64;
    int b    = blockIdx.z;
    int wd   = wid >> 1;       // 0..1
    int wt   = wid & 1;        // 0..1

    float acc[3][4][4];
#pragma unroll
    for (int m = 0; m < 3; m++)
#pragma unroll
        for (int n = 0; n < 4; n++)
#pragma unroll
            for (int k = 0; k < 4; k++) acc[m][n][k] = 0.f;

    uint32_t sbase = smem_u32(smem);
    uint32_t laB = (uint32_t)((lane & 15) * BSTRIDE + (lane >> 4) * 16);

    // A-fragment base: warp covers mtiles (bx*6 + wd*3 + {0,1,2})
    const uint4* wfrag = g_Wfrag + (size_t)((blockIdx.x * 6 + wd * 3) * NKS) * 32 + lane;

    // X staging mapping: thread -> (c = pc, t = pt..pt+15), converted at load
    int pc = tid >> 2;             // 0..31
    int pt = (tid & 3) * 16;       // 0..48
    const float* Xbase = X + (size_t)b * C_ * T_ + t0 + pt;

    uint32_t xh[8];
    auto loadcvt = [&](int c) {
#pragma unroll
        for (int j = 0; j < 4; j++) {
            float4 v = *(const float4*)(Xbase + (size_t)c * T_ + j * 4);
            __half2 p0 = __floats2half2_rn(v.x, v.y);
            __half2 p1 = __floats2half2_rn(v.z, v.w);
            xh[2 * j]     = *(uint32_t*)&p0;
            xh[2 * j + 1] = *(uint32_t*)&p1;
        }
    };
    auto stsX = [&](uint8_t* buf) {
        uint32_t off = (uint32_t)(pc * BSTRIDE + pt * 2);
        *(uint4*)(buf + off)      = make_uint4(xh[0], xh[1], xh[2], xh[3]);
        *(uint4*)(buf + off + 16) = make_uint4(xh[4], xh[5], xh[6], xh[7]);
    };

    // ---------- prologue: stage chunk 0, prefetch chunk 1 ----------
    loadcvt(pc);
    stsX(smem);
    loadcvt(32 + pc);
    __syncthreads();

    // ---------- main loop: one sync per chunk ----------
    for (int ch = 0; ch < 9; ch++) {
        int cur = ch & 1;
        uint32_t bufo = (uint32_t)cur * BUFSZ;
        int nc = (ch == 8) ? 16 : 32;
        int nks = nc >> 4;

        // stage chunk ch+1 (from regs) + prefetch chunk ch+2 (overlaps MMA)
        if (ch < 8) {
            int ncn = (ch == 7) ? 16 : 32;
            uint8_t* nbuf = smem + (uint32_t)(cur ^ 1) * BUFSZ;
            if (pc < ncn) stsX(nbuf);
            if (ch < 7) {
                int nc2 = (ch == 6) ? 16 : 32;
                if (pc < nc2) loadcvt((ch + 2) * 32 + pc);
            }
        }

        // ---- mma on buf[cur] ----
        uint32_t Bh = sbase + bufo + (uint32_t)(wt * 64) + laB;

        for (int ks = 0; ks < nks; ks++) {
            uint4 af[3];
#pragma unroll
            for (int mt = 0; mt < 3; mt++)
                af[mt] = __ldg(wfrag + ((size_t)mt * NKS + (ch * 2 + ks)) * 32);

            uint32_t bo = (uint32_t)(ks * 16 * BSTRIDE);
            uint32_t bh[8];
            LDSM_X4_T(bh,     Bh + bo);
            LDSM_X4_T(bh + 4, Bh + bo + 32);

#pragma unroll
            for (int mt = 0; mt < 3; mt++) {
                uint32_t ah[4] = {af[mt].x, af[mt].y, af[mt].z, af[mt].w};
#pragma unroll
                for (int nt = 0; nt < 4; nt++)
                    MMA16816F(acc[mt][nt], ah, bh[2 * nt], bh[2 * nt + 1]);
            }
        }
        __syncthreads();
    }

    // ---- epilogue: fragment rows = d, cols = t ----
#pragma unroll
    for (int mt = 0; mt < 3; mt++) {
        int dr = d0 + wd * 48 + mt * 16 + (lane >> 2);
#pragma unroll
        for (int nt = 0; nt < 4; nt++) {
            int tt = t0 + wt * 32 + nt * 8 + (lane & 3) * 2;
            if (dr < D_)
                *(float2*)(out + ((size_t)b * D_ + dr) * T_ + tt) =
                    make_float2(acc[mt][nt][0], acc[mt][nt][1]);
            if (dr + 8 < D_)
                *(float2*)(out + ((size_t)b * D_ + dr + 8) * T_ + tt) =
                    make_float2(acc[mt][nt][2], acc[mt][nt][3]);
        }
    }
}

// ---------------------------------------------------------------------------
extern "C" void kernel_launch(void* const* d_in, const int* in_sizes, int n_in,
                              void* d_out, int out_size) {
    const float* X   = (const float*)d_in[0];
    const float* loc = (const float*)d_in[1];
    const float* zre = (const float*)d_in[2];
    const float* zim = (const float*)d_in[3];
    float* out = (float*)d_out;

    trig_kernel<<<KK_, C_>>>(loc);
    a_kernel<<<dim3(17, NCHUNK), 272>>>(zre, zim);
    softmax_kernel<<<D_, 256>>>();
    bdt_mma_kernel<<<dim3(3, 16, B_), 128>>>(X, out);
}